// round 2
// baseline (speedup 1.0000x reference)
#include <cuda_runtime.h>

#define N 8192
#define D 32
#define NUM_ITERS 100
#define STABF 1e-8f

// Static device scratch (allocation-free rule: __device__ globals)
__device__ float  g_K[(size_t)N * N];     // Gibbs kernel, fp32 (256 MB)
__device__ float  g_C[(size_t)N * N];     // cost matrix, fp32 (256 MB)
__device__ float  g_u[N];
__device__ float  g_v[N];
__device__ float  g_n1[N];
__device__ float  g_n2[N];
__device__ float  g_part[64 * N];         // column-matvec partials
__device__ double g_epart[N / 2];         // epilogue block partials
__device__ double g_w[3];                 // w_st, w_ss, w_tt

// exp(t) for t in [-30, 0], FMA-pipe only (no MUFU). ~4e-7 rel err.
__device__ __forceinline__ float fexp(float t) {
    const float LOG2E = 1.4426950408889634f;
    float y = fmaf(t, LOG2E, 12582912.0f);          // magic round-to-nearest
    int   k = __float_as_int(y) - 0x4B400000;       // integer part of t*log2e
    float r = y - 12582912.0f;
    float f = fmaf(t, LOG2E, -r);                   // frac in [-0.5, 0.5]
    float p = 1.5403530e-4f;
    p = fmaf(p, f, 1.33335581e-3f);
    p = fmaf(p, f, 9.61812911e-3f);
    p = fmaf(p, f, 5.55041087e-2f);
    p = fmaf(p, f, 2.40226507e-1f);
    p = fmaf(p, f, 6.93147181e-1f);
    p = fmaf(p, f, 1.0f);
    return p * __int_as_float((k + 127) << 23);     // * 2^k
}

// ---------------- squared norms ----------------
__global__ void norms_kernel(const float* __restrict__ X, float* __restrict__ nrm) {
    int i = blockIdx.x * blockDim.x + threadIdx.x;
    if (i >= N) return;
    const float4* x4 = (const float4*)(X + (size_t)i * D);
    float s = 0.f;
    #pragma unroll
    for (int k = 0; k < D / 4; k++) {
        float4 a = x4[k];
        s += a.x * a.x + a.y * a.y + a.z * a.z + a.w * a.w;
    }
    nrm[i] = s;
}

// ---------------- build K and C ----------------
// 64x64 tile per block, 256 threads, 4x4 micro-tile per thread.
__global__ __launch_bounds__(256) void build_kernel(
    const float* __restrict__ X1, const float* __restrict__ X2,
    const float* __restrict__ nrm1, const float* __restrict__ nrm2,
    float* __restrict__ Kout, float* __restrict__ Cout)
{
    __shared__ float s1[64][33];
    __shared__ float s2[64][33];
    int bi = blockIdx.y * 64;
    int bj = blockIdx.x * 64;

    for (int t = threadIdx.x; t < 64 * 32; t += 256) {
        int r = t >> 5, c = t & 31;
        s1[r][c] = X1[(size_t)(bi + r) * D + c];
        s2[r][c] = X2[(size_t)(bj + r) * D + c];
    }
    __syncthreads();

    int tj = (threadIdx.x & 15) * 4;
    int ti = (threadIdx.x >> 4) * 4;

    float acc[4][4];
    #pragma unroll
    for (int r = 0; r < 4; r++)
        #pragma unroll
        for (int c = 0; c < 4; c++) acc[r][c] = 0.f;

    #pragma unroll
    for (int k = 0; k < 32; k++) {
        float a0 = s1[ti + 0][k], a1 = s1[ti + 1][k], a2 = s1[ti + 2][k], a3 = s1[ti + 3][k];
        float b0 = s2[tj + 0][k], b1 = s2[tj + 1][k], b2 = s2[tj + 2][k], b3 = s2[tj + 3][k];
        acc[0][0] = fmaf(a0, b0, acc[0][0]); acc[0][1] = fmaf(a0, b1, acc[0][1]);
        acc[0][2] = fmaf(a0, b2, acc[0][2]); acc[0][3] = fmaf(a0, b3, acc[0][3]);
        acc[1][0] = fmaf(a1, b0, acc[1][0]); acc[1][1] = fmaf(a1, b1, acc[1][1]);
        acc[1][2] = fmaf(a1, b2, acc[1][2]); acc[1][3] = fmaf(a1, b3, acc[1][3]);
        acc[2][0] = fmaf(a2, b0, acc[2][0]); acc[2][1] = fmaf(a2, b1, acc[2][1]);
        acc[2][2] = fmaf(a2, b2, acc[2][2]); acc[2][3] = fmaf(a2, b3, acc[2][3]);
        acc[3][0] = fmaf(a3, b0, acc[3][0]); acc[3][1] = fmaf(a3, b1, acc[3][1]);
        acc[3][2] = fmaf(a3, b2, acc[3][2]); acc[3][3] = fmaf(a3, b3, acc[3][3]);
    }

    #pragma unroll
    for (int r = 0; r < 4; r++) {
        int row = bi + ti + r;
        float n1v = nrm1[row];
        float4 cv, kv;
        float c0 = fmaxf(fmaf(-2.f, acc[r][0], n1v + nrm2[bj + tj + 0]), 0.f);
        float c1 = fmaxf(fmaf(-2.f, acc[r][1], n1v + nrm2[bj + tj + 1]), 0.f);
        float c2 = fmaxf(fmaf(-2.f, acc[r][2], n1v + nrm2[bj + tj + 2]), 0.f);
        float c3 = fmaxf(fmaf(-2.f, acc[r][3], n1v + nrm2[bj + tj + 3]), 0.f);
        cv.x = c0; cv.y = c1; cv.z = c2; cv.w = c3;
        kv.x = fexp(-10.f * c0); kv.y = fexp(-10.f * c1);
        kv.z = fexp(-10.f * c2); kv.w = fexp(-10.f * c3);
        size_t off = (size_t)row * N + bj + tj;
        *(float4*)(Cout + off) = cv;
        *(float4*)(Kout + off) = kv;
    }
}

// ---------------- init u = 1 ----------------
__global__ void init_ones_kernel(float* __restrict__ u) {
    int i = blockIdx.x * blockDim.x + threadIdx.x;
    if (i < N) u[i] = 1.0f;
}

// ---------------- row matvec: out[i] = inv_n / (sum_j K[i][j]*vin[j] + stab) ----------------
// 8 rows per block, v cached in registers (one v read per block, not per row).
__global__ __launch_bounds__(256) void matvec_row_kernel(
    const float* __restrict__ Kmat, const float* __restrict__ vin,
    float* __restrict__ vout, float inv_n)
{
    __shared__ float sred[8][8];
    int row0 = blockIdx.x * 8;
    int t = threadIdx.x;

    float4 vr[8];
    const float4* v4 = (const float4*)vin;
    #pragma unroll
    for (int c = 0; c < 8; c++) vr[c] = v4[t + 256 * c];

    float acc[8];
    #pragma unroll
    for (int r = 0; r < 8; r++) {
        const float4* Kr = (const float4*)(Kmat + (size_t)(row0 + r) * N);
        float a = 0.f;
        #pragma unroll
        for (int c = 0; c < 8; c++) {
            float4 k4 = Kr[t + 256 * c];
            a = fmaf(k4.x, vr[c].x, a);
            a = fmaf(k4.y, vr[c].y, a);
            a = fmaf(k4.z, vr[c].z, a);
            a = fmaf(k4.w, vr[c].w, a);
        }
        acc[r] = a;
    }

    int lane = t & 31, wid = t >> 5;
    #pragma unroll
    for (int r = 0; r < 8; r++) {
        float a = acc[r];
        #pragma unroll
        for (int o = 16; o; o >>= 1) a += __shfl_down_sync(0xffffffffu, a, o);
        if (lane == 0) sred[r][wid] = a;
    }
    __syncthreads();
    if (t < 8) {
        float s = 0.f;
        #pragma unroll
        for (int w = 0; w < 8; w++) s += sred[t][w];
        vout[row0 + t] = inv_n / (s + STABF);
    }
}

// ---------------- column matvec partials: part[chunk][j] = sum_{r in chunk} K[r][j]*u[r] ----------------
__global__ __launch_bounds__(256) void matvec_col_kernel(
    const float* __restrict__ Kmat, const float* __restrict__ uin,
    float* __restrict__ part)
{
    int j4 = blockIdx.x * 256 + threadIdx.x;   // float4 column index [0, 2048)
    int r0 = blockIdx.y * 128;
    float4 acc = make_float4(0.f, 0.f, 0.f, 0.f);
    #pragma unroll 4
    for (int r = r0; r < r0 + 128; r++) {
        float4 k4 = ((const float4*)(Kmat + (size_t)r * N))[j4];
        float ur = __ldg(uin + r);
        acc.x = fmaf(k4.x, ur, acc.x);
        acc.y = fmaf(k4.y, ur, acc.y);
        acc.z = fmaf(k4.z, ur, acc.z);
        acc.w = fmaf(k4.w, ur, acc.w);
    }
    ((float4*)(part + (size_t)blockIdx.y * N))[j4] = acc;
}

// ---------------- v[j] = inv_n / (sum_c part[c][j] + stab), fixed order ----------------
__global__ void reduce_update_kernel(const float* __restrict__ part,
                                     float* __restrict__ vout, float inv_n) {
    int j = blockIdx.x * blockDim.x + threadIdx.x;
    if (j >= N) return;
    float s = 0.f;
    #pragma unroll
    for (int c = 0; c < 64; c++) s += part[(size_t)c * N + j];
    vout[j] = inv_n / (s + STABF);
}

// ---------------- epilogue: block partial of sum u_i K_ij C_ij v_j (2 rows per block) ----------------
__global__ __launch_bounds__(256) void epilogue_kernel(
    const float* __restrict__ Kmat, const float* __restrict__ Cmat,
    const float* __restrict__ u, const float* __restrict__ v,
    double* __restrict__ epart)
{
    __shared__ double sm[8];
    int row0 = blockIdx.x * 2;
    int t = threadIdx.x;
    const float4* v4 = (const float4*)v;

    float facc = 0.f;
    #pragma unroll
    for (int rr = 0; rr < 2; rr++) {
        int row = row0 + rr;
        float uu = __ldg(u + row);
        const float4* K4 = (const float4*)(Kmat + (size_t)row * N);
        const float4* C4 = (const float4*)(Cmat + (size_t)row * N);
        #pragma unroll
        for (int c = 0; c < 8; c++) {
            int idx = t + 256 * c;
            float4 k4 = K4[idx], c4 = C4[idx], vv = v4[idx];
            float term = k4.x * vv.x * c4.x + k4.y * vv.y * c4.y
                       + k4.z * vv.z * c4.z + k4.w * vv.w * c4.w;
            facc = fmaf(uu, term, facc);
        }
    }

    double a = (double)facc;
    #pragma unroll
    for (int o = 16; o; o >>= 1) a += __shfl_down_sync(0xffffffffu, a, o);
    int lane = t & 31, wid = t >> 5;
    if (lane == 0) sm[wid] = a;
    __syncthreads();
    if (t == 0) {
        double s = 0.0;
        #pragma unroll
        for (int w = 0; w < 8; w++) s += sm[w];
        epart[blockIdx.x] = s;
    }
}

__global__ void reduce_w_kernel(const double* __restrict__ epart, double* __restrict__ wout) {
    __shared__ double sm[256];
    int t = threadIdx.x;
    double s = 0.0;
    for (int i = t; i < N / 2; i += 256) s += epart[i];
    sm[t] = s;
    __syncthreads();
    for (int o = 128; o; o >>= 1) {
        if (t < o) sm[t] += sm[t + o];
        __syncthreads();
    }
    if (t == 0) *wout = sm[0];
}

__global__ void combine_kernel(const double* __restrict__ w, float* __restrict__ out) {
    out[0] = (float)((w[0] - 0.5 * (w[1] + w[2])) / (double)N);
}

// ---------------- driver ----------------
extern "C" void kernel_launch(void* const* d_in, const int* in_sizes, int n_in,
                              void* d_out, int out_size) {
    const float* src = (const float*)d_in[0];
    const float* tgt = (const float*)d_in[1];
    float* out = (float*)d_out;

    float *K, *C, *u, *v, *pn1, *pn2, *part;
    double *epart, *w;
    cudaGetSymbolAddress((void**)&K, g_K);
    cudaGetSymbolAddress((void**)&C, g_C);
    cudaGetSymbolAddress((void**)&u, g_u);
    cudaGetSymbolAddress((void**)&v, g_v);
    cudaGetSymbolAddress((void**)&pn1, g_n1);
    cudaGetSymbolAddress((void**)&pn2, g_n2);
    cudaGetSymbolAddress((void**)&part, g_part);
    cudaGetSymbolAddress((void**)&epart, g_epart);
    cudaGetSymbolAddress((void**)&w, g_w);

    const float inv_n = 1.0f / (float)N;

    for (int p = 0; p < 3; p++) {
        // p=0: (src,tgt)  p=1: (src,src)  p=2: (tgt,tgt)
        const float* x1 = (p == 2) ? tgt : src;
        const float* x2 = (p == 1) ? src : tgt;

        norms_kernel<<<N / 256, 256>>>(x1, pn1);
        norms_kernel<<<N / 256, 256>>>(x2, pn2);
        build_kernel<<<dim3(N / 64, N / 64), 256>>>(x1, x2, pn1, pn2, K, C);
        init_ones_kernel<<<N / 256, 256>>>(u);

        for (int it = 0; it < NUM_ITERS; it++) {
            if (p == 0) {
                // v = nu / (K^T u + stab): chunked column sums, deterministic reduce
                matvec_col_kernel<<<dim3(N / 1024, 64), 256>>>(K, u, part);
                reduce_update_kernel<<<N / 256, 256>>>(part, v, inv_n);
            } else {
                // K symmetric: K^T u == K u
                matvec_row_kernel<<<N / 8, 256>>>(K, u, v, inv_n);
            }
            // u = mu / (K v + stab)
            matvec_row_kernel<<<N / 8, 256>>>(K, v, u, inv_n);
        }

        epilogue_kernel<<<N / 2, 256>>>(K, C, u, v, epart);
        reduce_w_kernel<<<1, 256>>>(epart, w + p);
    }

    combine_kernel<<<1, 1>>>(w, out);
}

// round 3
// speedup vs baseline: 1.4676x; 1.4676x over previous
#include <cuda_runtime.h>
#include <cuda_bf16.h>

#define N 8192
#define D 32
#define NUM_ITERS 100
#define STABF 1e-8f

// Static device scratch (allocation-free rule: __device__ globals)
__device__ __nv_bfloat16 g_K[(size_t)N * N];   // Gibbs kernel, bf16 (128 MB)
__device__ float  g_C[(size_t)N * N];          // cost matrix, fp32 (256 MB)
__device__ float  g_u[N];
__device__ float  g_v[N];
__device__ float  g_n1[N];
__device__ float  g_n2[N];
__device__ float  g_part[128 * N];             // column-matvec partials (fp32)
__device__ double g_epart[N / 2];              // epilogue block partials
__device__ double g_w[3];                      // w_st, w_ss, w_tt

// exp(t) for t in [-30, 0], FMA-pipe only (no MUFU). ~4e-7 rel err.
__device__ __forceinline__ float fexp(float t) {
    const float LOG2E = 1.4426950408889634f;
    float y = fmaf(t, LOG2E, 12582912.0f);          // magic round-to-nearest
    int   k = __float_as_int(y) - 0x4B400000;       // integer part of t*log2e
    float r = y - 12582912.0f;
    float f = fmaf(t, LOG2E, -r);                   // frac in [-0.5, 0.5]
    float p = 1.5403530e-4f;
    p = fmaf(p, f, 1.33335581e-3f);
    p = fmaf(p, f, 9.61812911e-3f);
    p = fmaf(p, f, 5.55041087e-2f);
    p = fmaf(p, f, 2.40226507e-1f);
    p = fmaf(p, f, 6.93147181e-1f);
    p = fmaf(p, f, 1.0f);
    return p * __int_as_float((k + 127) << 23);     // * 2^k
}

// ---------------- squared norms ----------------
__global__ void norms_kernel(const float* __restrict__ X, float* __restrict__ nrm) {
    int i = blockIdx.x * blockDim.x + threadIdx.x;
    if (i >= N) return;
    const float4* x4 = (const float4*)(X + (size_t)i * D);
    float s = 0.f;
    #pragma unroll
    for (int k = 0; k < D / 4; k++) {
        float4 a = x4[k];
        s += a.x * a.x + a.y * a.y + a.z * a.z + a.w * a.w;
    }
    nrm[i] = s;
}

// ---------------- build K (bf16) and C (fp32) ----------------
// 64x64 tile per block, 256 threads, 4x4 micro-tile per thread.
__global__ __launch_bounds__(256) void build_kernel(
    const float* __restrict__ X1, const float* __restrict__ X2,
    const float* __restrict__ nrm1, const float* __restrict__ nrm2,
    __nv_bfloat16* __restrict__ Kout, float* __restrict__ Cout)
{
    __shared__ float s1[64][33];
    __shared__ float s2[64][33];
    int bi = blockIdx.y * 64;
    int bj = blockIdx.x * 64;

    for (int t = threadIdx.x; t < 64 * 32; t += 256) {
        int r = t >> 5, c = t & 31;
        s1[r][c] = X1[(size_t)(bi + r) * D + c];
        s2[r][c] = X2[(size_t)(bj + r) * D + c];
    }
    __syncthreads();

    int tj = (threadIdx.x & 15) * 4;
    int ti = (threadIdx.x >> 4) * 4;

    float acc[4][4];
    #pragma unroll
    for (int r = 0; r < 4; r++)
        #pragma unroll
        for (int c = 0; c < 4; c++) acc[r][c] = 0.f;

    #pragma unroll
    for (int k = 0; k < 32; k++) {
        float a0 = s1[ti + 0][k], a1 = s1[ti + 1][k], a2 = s1[ti + 2][k], a3 = s1[ti + 3][k];
        float b0 = s2[tj + 0][k], b1 = s2[tj + 1][k], b2 = s2[tj + 2][k], b3 = s2[tj + 3][k];
        acc[0][0] = fmaf(a0, b0, acc[0][0]); acc[0][1] = fmaf(a0, b1, acc[0][1]);
        acc[0][2] = fmaf(a0, b2, acc[0][2]); acc[0][3] = fmaf(a0, b3, acc[0][3]);
        acc[1][0] = fmaf(a1, b0, acc[1][0]); acc[1][1] = fmaf(a1, b1, acc[1][1]);
        acc[1][2] = fmaf(a1, b2, acc[1][2]); acc[1][3] = fmaf(a1, b3, acc[1][3]);
        acc[2][0] = fmaf(a2, b0, acc[2][0]); acc[2][1] = fmaf(a2, b1, acc[2][1]);
        acc[2][2] = fmaf(a2, b2, acc[2][2]); acc[2][3] = fmaf(a2, b3, acc[2][3]);
        acc[3][0] = fmaf(a3, b0, acc[3][0]); acc[3][1] = fmaf(a3, b1, acc[3][1]);
        acc[3][2] = fmaf(a3, b2, acc[3][2]); acc[3][3] = fmaf(a3, b3, acc[3][3]);
    }

    #pragma unroll
    for (int r = 0; r < 4; r++) {
        int row = bi + ti + r;
        float n1v = nrm1[row];
        float c0 = fmaxf(fmaf(-2.f, acc[r][0], n1v + nrm2[bj + tj + 0]), 0.f);
        float c1 = fmaxf(fmaf(-2.f, acc[r][1], n1v + nrm2[bj + tj + 1]), 0.f);
        float c2 = fmaxf(fmaf(-2.f, acc[r][2], n1v + nrm2[bj + tj + 2]), 0.f);
        float c3 = fmaxf(fmaf(-2.f, acc[r][3], n1v + nrm2[bj + tj + 3]), 0.f);
        float4 cv; cv.x = c0; cv.y = c1; cv.z = c2; cv.w = c3;
        __nv_bfloat162 k01 = __floats2bfloat162_rn(fexp(-10.f * c0), fexp(-10.f * c1));
        __nv_bfloat162 k23 = __floats2bfloat162_rn(fexp(-10.f * c2), fexp(-10.f * c3));
        size_t off = (size_t)row * N + bj + tj;
        *(float4*)(Cout + off) = cv;
        uint2 kpack;
        kpack.x = *(unsigned*)&k01;
        kpack.y = *(unsigned*)&k23;
        *(uint2*)(Kout + off) = kpack;
    }
}

// ---------------- init u = 1 ----------------
__global__ void init_ones_kernel(float* __restrict__ u) {
    int i = blockIdx.x * blockDim.x + threadIdx.x;
    if (i < N) u[i] = 1.0f;
}

// ---------------- row matvec: out[i] = inv_n / (sum_j K[i][j]*vin[j] + stab) ----------------
// 32 rows per block, v staged in shared memory once per block.
#define RPB 32
__global__ __launch_bounds__(256) void matvec_row_kernel(
    const __nv_bfloat16* __restrict__ Kmat, const float* __restrict__ vin,
    float* __restrict__ vout, float inv_n)
{
    __shared__ float sv[N];            // 32 KB
    __shared__ float sred[RPB][8];
    int row0 = blockIdx.x * RPB;
    int t = threadIdx.x;

    const float4* v4 = (const float4*)vin;
    float4* sv4 = (float4*)sv;
    #pragma unroll
    for (int c = 0; c < 8; c++) sv4[t + 256 * c] = v4[t + 256 * c];
    __syncthreads();

    int lane = t & 31, wid = t >> 5;
    #pragma unroll 2
    for (int r = 0; r < RPB; r++) {
        const uint4* Kr = (const uint4*)(Kmat + (size_t)(row0 + r) * N);
        float a = 0.f;
        #pragma unroll
        for (int c = 0; c < 4; c++) {
            int i16 = c * 256 + t;                   // uint4 (8 bf16) index
            uint4 kk = Kr[i16];
            float4 va = sv4[i16 * 2], vb = sv4[i16 * 2 + 1];
            float2 f0 = __bfloat1622float2(*(__nv_bfloat162*)&kk.x);
            float2 f1 = __bfloat1622float2(*(__nv_bfloat162*)&kk.y);
            float2 f2 = __bfloat1622float2(*(__nv_bfloat162*)&kk.z);
            float2 f3 = __bfloat1622float2(*(__nv_bfloat162*)&kk.w);
            a = fmaf(f0.x, va.x, a); a = fmaf(f0.y, va.y, a);
            a = fmaf(f1.x, va.z, a); a = fmaf(f1.y, va.w, a);
            a = fmaf(f2.x, vb.x, a); a = fmaf(f2.y, vb.y, a);
            a = fmaf(f3.x, vb.z, a); a = fmaf(f3.y, vb.w, a);
        }
        #pragma unroll
        for (int o = 16; o; o >>= 1) a += __shfl_down_sync(0xffffffffu, a, o);
        if (lane == 0) sred[r][wid] = a;
    }
    __syncthreads();
    if (t < RPB) {
        float s = 0.f;
        #pragma unroll
        for (int w = 0; w < 8; w++) s += sred[t][w];
        vout[row0 + t] = inv_n / (s + STABF);
    }
}

// ---------------- column matvec partials: part[chunk][j] = sum_{r in chunk} K[r][j]*u[r] ----------------
#define CCHUNK 64
__global__ __launch_bounds__(256) void matvec_col_kernel(
    const __nv_bfloat16* __restrict__ Kmat, const float* __restrict__ uin,
    float* __restrict__ part)
{
    int j16 = blockIdx.x * 256 + threadIdx.x;   // uint4 (8 bf16) column index [0, 1024)
    int r0 = blockIdx.y * CCHUNK;
    float acc[8];
    #pragma unroll
    for (int e = 0; e < 8; e++) acc[e] = 0.f;

    #pragma unroll 4
    for (int rr = 0; rr < CCHUNK; rr++) {
        int r = r0 + rr;
        uint4 kk = ((const uint4*)(Kmat + (size_t)r * N))[j16];
        float ur = __ldg(uin + r);
        float2 f0 = __bfloat1622float2(*(__nv_bfloat162*)&kk.x);
        float2 f1 = __bfloat1622float2(*(__nv_bfloat162*)&kk.y);
        float2 f2 = __bfloat1622float2(*(__nv_bfloat162*)&kk.z);
        float2 f3 = __bfloat1622float2(*(__nv_bfloat162*)&kk.w);
        acc[0] = fmaf(f0.x, ur, acc[0]); acc[1] = fmaf(f0.y, ur, acc[1]);
        acc[2] = fmaf(f1.x, ur, acc[2]); acc[3] = fmaf(f1.y, ur, acc[3]);
        acc[4] = fmaf(f2.x, ur, acc[4]); acc[5] = fmaf(f2.y, ur, acc[5]);
        acc[6] = fmaf(f3.x, ur, acc[6]); acc[7] = fmaf(f3.y, ur, acc[7]);
    }
    float4* p4 = (float4*)(part + (size_t)blockIdx.y * N);
    p4[j16 * 2]     = make_float4(acc[0], acc[1], acc[2], acc[3]);
    p4[j16 * 2 + 1] = make_float4(acc[4], acc[5], acc[6], acc[7]);
}

// ---------------- v[j] = inv_n / (sum_c part[c][j] + stab), fixed order ----------------
__global__ void reduce_update_kernel(const float* __restrict__ part,
                                     float* __restrict__ vout, float inv_n) {
    int j = blockIdx.x * blockDim.x + threadIdx.x;
    if (j >= N) return;
    float s = 0.f;
    #pragma unroll
    for (int c = 0; c < N / CCHUNK; c++) s += part[(size_t)c * N + j];
    vout[j] = inv_n / (s + STABF);
}

// ---------------- epilogue: block partial of sum u_i K_ij C_ij v_j ----------------
// K recomputed in fp32 from C (removes direct bf16 error from the cost evaluation).
__global__ __launch_bounds__(256) void epilogue_kernel(
    const float* __restrict__ Cmat,
    const float* __restrict__ u, const float* __restrict__ v,
    double* __restrict__ epart)
{
    __shared__ double sm[8];
    int row0 = blockIdx.x * 2;
    int t = threadIdx.x;
    const float4* v4 = (const float4*)v;

    float facc = 0.f;
    #pragma unroll
    for (int rr = 0; rr < 2; rr++) {
        int row = row0 + rr;
        float uu = __ldg(u + row);
        const float4* C4 = (const float4*)(Cmat + (size_t)row * N);
        #pragma unroll
        for (int c = 0; c < 8; c++) {
            int idx = t + 256 * c;
            float4 c4 = C4[idx], vv = v4[idx];
            float k0 = fexp(-10.f * c4.x), k1 = fexp(-10.f * c4.y);
            float k2 = fexp(-10.f * c4.z), k3 = fexp(-10.f * c4.w);
            float term = k0 * vv.x * c4.x + k1 * vv.y * c4.y
                       + k2 * vv.z * c4.z + k3 * vv.w * c4.w;
            facc = fmaf(uu, term, facc);
        }
    }

    double a = (double)facc;
    #pragma unroll
    for (int o = 16; o; o >>= 1) a += __shfl_down_sync(0xffffffffu, a, o);
    int lane = t & 31, wid = t >> 5;
    if (lane == 0) sm[wid] = a;
    __syncthreads();
    if (t == 0) {
        double s = 0.0;
        #pragma unroll
        for (int w = 0; w < 8; w++) s += sm[w];
        epart[blockIdx.x] = s;
    }
}

__global__ void reduce_w_kernel(const double* __restrict__ epart, double* __restrict__ wout) {
    __shared__ double sm[256];
    int t = threadIdx.x;
    double s = 0.0;
    for (int i = t; i < N / 2; i += 256) s += epart[i];
    sm[t] = s;
    __syncthreads();
    for (int o = 128; o; o >>= 1) {
        if (t < o) sm[t] += sm[t + o];
        __syncthreads();
    }
    if (t == 0) *wout = sm[0];
}

__global__ void combine_kernel(const double* __restrict__ w, float* __restrict__ out) {
    out[0] = (float)((w[0] - 0.5 * (w[1] + w[2])) / (double)N);
}

// ---------------- driver ----------------
extern "C" void kernel_launch(void* const* d_in, const int* in_sizes, int n_in,
                              void* d_out, int out_size) {
    const float* src = (const float*)d_in[0];
    const float* tgt = (const float*)d_in[1];
    float* out = (float*)d_out;

    __nv_bfloat16* K;
    float *C, *u, *v, *pn1, *pn2, *part;
    double *epart, *w;
    cudaGetSymbolAddress((void**)&K, g_K);
    cudaGetSymbolAddress((void**)&C, g_C);
    cudaGetSymbolAddress((void**)&u, g_u);
    cudaGetSymbolAddress((void**)&v, g_v);
    cudaGetSymbolAddress((void**)&pn1, g_n1);
    cudaGetSymbolAddress((void**)&pn2, g_n2);
    cudaGetSymbolAddress((void**)&part, g_part);
    cudaGetSymbolAddress((void**)&epart, g_epart);
    cudaGetSymbolAddress((void**)&w, g_w);

    const float inv_n = 1.0f / (float)N;

    for (int p = 0; p < 3; p++) {
        // p=0: (src,tgt)  p=1: (src,src)  p=2: (tgt,tgt)
        const float* x1 = (p == 2) ? tgt : src;
        const float* x2 = (p == 1) ? src : tgt;

        norms_kernel<<<N / 256, 256>>>(x1, pn1);
        norms_kernel<<<N / 256, 256>>>(x2, pn2);
        build_kernel<<<dim3(N / 64, N / 64), 256>>>(x1, x2, pn1, pn2, K, C);
        init_ones_kernel<<<N / 256, 256>>>(u);

        for (int it = 0; it < NUM_ITERS; it++) {
            if (p == 0) {
                // v = nu / (K^T u + stab): chunked column sums, deterministic reduce
                matvec_col_kernel<<<dim3(4, N / CCHUNK), 256>>>(K, u, part);
                reduce_update_kernel<<<N / 256, 256>>>(part, v, inv_n);
            } else {
                // K symmetric: K^T u == K u
                matvec_row_kernel<<<N / RPB, 256>>>(K, u, v, inv_n);
            }
            // u = mu / (K v + stab)
            matvec_row_kernel<<<N / RPB, 256>>>(K, v, u, inv_n);
        }

        epilogue_kernel<<<N / 2, 256>>>(C, u, v, epart);
        reduce_w_kernel<<<1, 256>>>(epart, w + p);
    }

    combine_kernel<<<1, 1>>>(w, out);
}